// round 9
// baseline (speedup 1.0000x reference)
#include <cuda_runtime.h>

typedef unsigned long long u64;

#define H_      51
#define TSTEPS  512
#define BTOT    1024
#define NB      8
#define NBLK    (BTOT / NB)        // 128
#define NTHR    512
#define GP      224                // padded gate slots (204 -> 224)
#define PR1     224                // partial row stride per batch (floats)
#define LVL     (NB * PR1)         // 1792 floats per partial level
#define HROWS   110                // h rows: 0..50 h1, 51..53 pad, 54..104 h2, 105..109 pad
#define H2B     54                 // h2 base row

// ---- shared memory layout (float offsets) ----
#define OFF_W1   0                         // [54][224]
#define OFF_W2   (OFF_W1 + 54*GP)          // [110][224]
#define OFF_HP   (OFF_W2 + 110*GP)         // hpair [110][8] floats (u64 pairs)
#define OFF_C1   (OFF_HP + HROWS*8)        // [8][52]
#define OFF_C2   (OFF_C1 + 8*52)           // [8][52]
#define OFF_PB1  (OFF_C2 + 8*52)           // 3 levels x [8][224]
#define OFF_PB2  (OFF_PB1 + 3*LVL)         // 6 levels x [8][224]
#define OFF_B1   (OFF_PB2 + 6*LVL)         // 224 (permuted (u,q))
#define OFF_B2   (OFF_B1 + GP)             // 224
#define OFF_WL   (OFF_B2 + GP)             // 56
#define OFF_BL   (OFF_WL + 56)             // 4
#define OFF_XR   (OFF_BL + 4)              // x ring [4][8] floats (pair layout)
#define SMEM_FLOATS (OFF_XR + 32)
#define SMEM_BYTES  (SMEM_FLOATS * 4)      // ~220.5 KB

__device__ __forceinline__ void ffma2(u64 &d, u64 a, u64 b) {
    asm("fma.rn.f32x2 %0, %1, %2, %0;" : "+l"(d) : "l"(a), "l"(b));
}
__device__ __forceinline__ float2 unpk(u64 v) {
    float2 r;
    asm("mov.b64 {%0, %1}, %2;" : "=f"(r.x), "=f"(r.y) : "l"(v));
    return r;
}
__device__ __forceinline__ u64 dup2(float w) {
    u64 d;
    asm("mov.b64 %0, {%1, %1};" : "=l"(d) : "f"(w));
    return d;
}
__device__ __forceinline__ float sigf(float x) {
    return __fdividef(1.0f, 1.0f + __expf(-x));
}
__device__ __forceinline__ float tanhfast(float x) {
    return __fdividef(2.0f, 1.0f + __expf(-2.0f * x)) - 1.0f;
}

// batch-paired gate GEMV over CNT k-rows + de-interleaved partial store.
// lane = gate slot s = lane + 32*(jbase+j). acc[j][bp]: lo = batch bp, hi = bp+4.
template<int CNT, int NJ, bool ADDX>
__device__ __forceinline__ void gemv_store(
    const float* __restrict__ wrow,       // W + k0*GP + lane + 32*jbase
    const ulonglong2* __restrict__ hp,    // hpair base + 2*k0
    float* __restrict__ pb,               // partial level base + lane + 32*jbase
    const u64* __restrict__ wi,           // dup'd Wih1 regs (ADDX only)
    const ulonglong2* __restrict__ xp)    // x pair row (2 entries, ADDX only)
{
    u64 acc[NJ][4];
#pragma unroll
    for (int j = 0; j < NJ; j++)
#pragma unroll
        for (int bp = 0; bp < 4; bp++) acc[j][bp] = 0ull;

    if (ADDX) {
        ulonglong2 xa = xp[0], xb = xp[1];
#pragma unroll
        for (int j = 0; j < NJ; j++) {
            ffma2(acc[j][0], wi[j], xa.x);
            ffma2(acc[j][1], wi[j], xa.y);
            ffma2(acc[j][2], wi[j], xb.x);
            ffma2(acc[j][3], wi[j], xb.y);
        }
    }
#pragma unroll
    for (int i = 0; i < CNT; i++) {
        ulonglong2 hA = hp[2 * i];
        ulonglong2 hB = hp[2 * i + 1];
#pragma unroll
        for (int j = 0; j < NJ; j++) {
            u64 wd = dup2(wrow[i * GP + 32 * j]);
            ffma2(acc[j][0], wd, hA.x);
            ffma2(acc[j][1], wd, hA.y);
            ffma2(acc[j][2], wd, hB.x);
            ffma2(acc[j][3], wd, hB.y);
        }
    }
#pragma unroll
    for (int j = 0; j < NJ; j++)
#pragma unroll
        for (int bp = 0; bp < 4; bp++) {
            float2 p = unpk(acc[j][bp]);
            pb[32 * j + bp * PR1]       = p.x;
            pb[32 * j + (bp + 4) * PR1] = p.y;
        }
}

// pointwise update: thread (b = tid>>6, u = tid&63), active u<51.
// Gate slots permuted (u,q): float4 per level. Level counts are warp-uniform
// (u<32 -> jA columns: L2 6 / L1 3 levels; u>=32 -> jB: 5 / 2).
__device__ __forceinline__ void cell_update(float* sm, int b, int u, bool act,
                                            bool doU2, bool doU1)
{
    if (!act) return;
    const bool hi = (u < 32);
    if (doU2) {
        const float4* p2 = (const float4*)(sm + OFF_PB2 + b * PR1 + 4 * u);
        float4 g = *(const float4*)(sm + OFF_B2 + 4 * u);
#pragma unroll
        for (int l = 0; l < 5; l++) {
            float4 p = p2[l * (LVL / 4)];
            g.x += p.x; g.y += p.y; g.z += p.z; g.w += p.w;
        }
        if (hi) {
            float4 p = p2[5 * (LVL / 4)];
            g.x += p.x; g.y += p.y; g.z += p.z; g.w += p.w;
        }
        float c  = sm[OFF_C2 + b * 52 + u];
        float cn = sigf(g.y) * c + sigf(g.x) * tanhfast(g.z);
        float hn = sigf(g.w) * tanhfast(cn);
        sm[OFF_C2 + b * 52 + u] = cn;
        sm[OFF_HP + (H2B + u) * 8 + (b & 3) * 2 + (b >> 2)] = hn;
    }
    if (doU1) {
        const float4* p1 = (const float4*)(sm + OFF_PB1 + b * PR1 + 4 * u);
        float4 g = *(const float4*)(sm + OFF_B1 + 4 * u);
#pragma unroll
        for (int l = 0; l < 2; l++) {
            float4 p = p1[l * (LVL / 4)];
            g.x += p.x; g.y += p.y; g.z += p.z; g.w += p.w;
        }
        if (hi) {
            float4 p = p1[2 * (LVL / 4)];
            g.x += p.x; g.y += p.y; g.z += p.z; g.w += p.w;
        }
        float c  = sm[OFF_C1 + b * 52 + u];
        float cn = sigf(g.y) * c + sigf(g.x) * tanhfast(g.z);
        float hn = sigf(g.w) * tanhfast(cn);
        sm[OFF_C1 + b * 52 + u] = cn;
        sm[OFF_HP + u * 8 + (b & 3) * 2 + (b >> 2)] = hn;
    }
}

__device__ __forceinline__ void out_phase(const float* sm, int lane, int bid,
                                          int tcol, float* __restrict__ out)
{
    int ob = lane & 7, part = lane >> 3;            // 4 parts x 13 k
    float a = 0.0f;
#pragma unroll
    for (int kk = 0; kk < 13; kk++) {
        int k = part * 13 + kk;                     // k=51 -> zero pad row
        a = fmaf(sm[OFF_HP + (H2B + k) * 8 + (ob & 3) * 2 + (ob >> 2)],
                 sm[OFF_WL + k], a);
    }
    a += __shfl_xor_sync(0xffffffffu, a, 8);
    a += __shfl_xor_sync(0xffffffffu, a, 16);
    if (lane < 8)
        out[(bid * NB + ob) * TSTEPS + tcol] = a + sm[OFF_BL];
}

__global__ void __launch_bounds__(NTHR, 1)
lstm_kernel(const float* __restrict__ input,
            const float* __restrict__ Wih1, const float* __restrict__ Whh1,
            const float* __restrict__ bih1, const float* __restrict__ bhh1,
            const float* __restrict__ Wih2, const float* __restrict__ Whh2,
            const float* __restrict__ bih2, const float* __restrict__ bhh2,
            const float* __restrict__ Wlin, const float* __restrict__ blin,
            float* __restrict__ out)
{
    extern __shared__ float sm[];
    const int tid  = threadIdx.x;
    const int bid  = blockIdx.x;
    const int lane = tid & 31;
    const int wid  = tid >> 5;            // 0..15

    // ---- staging ----
    for (int i = tid; i < HROWS * 8; i += NTHR) sm[OFF_HP + i] = 0.0f;
    for (int i = tid; i < 8 * 52 * 2; i += NTHR) sm[OFF_C1 + i] = 0.0f;

    // W1[k][s]: k<51 -> Whh1[og][k]; rows 51..53 zero. og = q*51+u, s=(u<<2)|q
    for (int i = tid; i < 54 * GP; i += NTHR) {
        int k = i / GP, s = i % GP, u = s >> 2, q = s & 3;
        float v = 0.0f;
        if (k < H_ && u < H_) v = Whh1[(q * H_ + u) * H_ + k];
        sm[OFF_W1 + i] = v;
    }
    // W2[k][s]: k<51 -> Wih2; k in [54,105) -> Whh2[k-54]; else zero
    for (int i = tid; i < 110 * GP; i += NTHR) {
        int k = i / GP, s = i % GP, u = s >> 2, q = s & 3;
        float v = 0.0f;
        if (u < H_) {
            if (k < H_)                            v = Wih2[(q * H_ + u) * H_ + k];
            else if (k >= H2B && k < H2B + H_)     v = Whh2[(q * H_ + u) * H_ + (k - H2B)];
        }
        sm[OFF_W2 + i] = v;
    }
    for (int i = tid; i < GP; i += NTHR) {
        int u = i >> 2, q = i & 3;
        float b1 = 0.0f, b2 = 0.0f;
        if (u < H_) {
            int og = q * H_ + u;
            b1 = bih1[og] + bhh1[og];
            b2 = bih2[og] + bhh2[og];
        }
        sm[OFF_B1 + i] = b1;
        sm[OFF_B2 + i] = b2;
    }
    if (tid < 56) sm[OFF_WL + tid] = (tid < H_) ? Wlin[tid] : 0.0f;
    if (tid == 0) sm[OFF_BL] = blin[0];
    // prefetch x(0..2) into pair-layout ring
    if (tid < 24) {
        int t = tid >> 3, b = tid & 7;
        sm[OFF_XR + t * 8 + (b & 3) * 2 + (b >> 2)] =
            input[t * BTOT + bid * NB + b];
    }
    __syncthreads();

    // ---- per-warp gemv role ----
    // w0..2:  L1 jA (NJ4) k-ranges 18/18/18 over rows [0,54)   -> PB1 lvl 0..2
    // w3..4:  L1 jB (NJ3) 27/27                                 -> PB1 lvl 0..1
    // w5..10: L2 jA (NJ4) 18x6 over rows [0,108)                -> PB2 lvl 0..5
    // w11..15:L2 jB (NJ3) 22x5 over rows [0,110)                -> PB2 lvl 0..4
    const bool isL1 = (wid < 5);
    int k0, jbase, woff, pboff, level;
    if (wid < 3)       { k0 = 18 * wid;        jbase = 0; woff = OFF_W1; pboff = OFF_PB1; level = wid; }
    else if (wid < 5)  { k0 = 27 * (wid - 3);  jbase = 4; woff = OFF_W1; pboff = OFF_PB1; level = wid - 3; }
    else if (wid < 11) { k0 = 18 * (wid - 5);  jbase = 0; woff = OFF_W2; pboff = OFF_PB2; level = wid - 5; }
    else               { k0 = 22 * (wid - 11); jbase = 4; woff = OFF_W2; pboff = OFF_PB2; level = wid - 11; }

    const float* wrow = sm + woff + k0 * GP + lane + 32 * jbase;
    const ulonglong2* hp = (const ulonglong2*)(sm + OFF_HP) + 2 * k0;
    float* pb = sm + pboff + level * LVL + lane + 32 * jbase;

    // dup'd Wih1 for the x-term (kh0 warps only)
    u64 wi[4];
    {
        int nj = (wid == 0) ? 4 : ((wid == 3) ? 3 : 0);
#pragma unroll
        for (int j = 0; j < 4; j++) {
            float v = 0.0f;
            if (j < nj) {
                int s = lane + 32 * (jbase + j), u = s >> 2, q = s & 3;
                if (u < H_) v = Wih1[q * H_ + u];
            }
            wi[j] = dup2(v);
        }
    }

    const int ub = tid >> 6;              // update batch 0..7
    const int uu = tid & 63;              // update unit
    const bool uact = (uu < H_);

    // ---- prologue: G1(0), U1(0) ----
    if (isL1) {
        const ulonglong2* xp = (const ulonglong2*)(sm + OFF_XR);
        if (wid == 0)      gemv_store<18, 4, true >(wrow, hp, pb, wi, xp);
        else if (wid < 3)  gemv_store<18, 4, false>(wrow, hp, pb, wi, xp);
        else if (wid == 3) gemv_store<27, 3, true >(wrow, hp, pb, wi, xp);
        else               gemv_store<27, 3, false>(wrow, hp, pb, wi, xp);
    }
    __syncthreads();
    cell_update(sm, ub, uu, uact, false, true);
    __syncthreads();

    // ---- pipelined recurrence ----
    for (int t = 0; t < TSTEPS; t++) {
        if (isL1) {
            if (t + 1 < TSTEPS) {
                const ulonglong2* xp =
                    (const ulonglong2*)(sm + OFF_XR) + ((t + 1) & 3) * 2;
                if (wid == 0)      gemv_store<18, 4, true >(wrow, hp, pb, wi, xp);
                else if (wid < 3)  gemv_store<18, 4, false>(wrow, hp, pb, wi, xp);
                else if (wid == 3) gemv_store<27, 3, true >(wrow, hp, pb, wi, xp);
                else               gemv_store<27, 3, false>(wrow, hp, pb, wi, xp);
            }
        } else {
            if (wid < 11) gemv_store<18, 4, false>(wrow, hp, pb, wi, nullptr);
            else          gemv_store<22, 3, false>(wrow, hp, pb, wi, nullptr);
            if (wid == 14 && t > 0) out_phase(sm, lane, bid, t - 1, out);
            if (wid == 15 && lane < 8 && t + 3 < TSTEPS) {
                float xv = input[(t + 3) * BTOT + bid * NB + lane];
                sm[OFF_XR + ((t + 3) & 3) * 8 + (lane & 3) * 2 + (lane >> 2)] = xv;
            }
        }
        __syncthreads();
        cell_update(sm, ub, uu, uact, true, t + 1 < TSTEPS);
        __syncthreads();
    }

    // ---- epilogue ----
    if (wid == 14) out_phase(sm, lane, bid, TSTEPS - 1, out);
}

extern "C" void kernel_launch(void* const* d_in, const int* in_sizes, int n_in,
                              void* d_out, int out_size)
{
    const float* input = (const float*)d_in[0];
    const float* Wih1  = (const float*)d_in[1];
    const float* Whh1  = (const float*)d_in[2];
    const float* bih1  = (const float*)d_in[3];
    const float* bhh1  = (const float*)d_in[4];
    const float* Wih2  = (const float*)d_in[5];
    const float* Whh2  = (const float*)d_in[6];
    const float* bih2  = (const float*)d_in[7];
    const float* bhh2  = (const float*)d_in[8];
    const float* Wlin  = (const float*)d_in[9];
    const float* blin  = (const float*)d_in[10];
    float* out = (float*)d_out;

    static bool attr_set = false;
    if (!attr_set) {
        cudaFuncSetAttribute(lstm_kernel,
                             cudaFuncAttributeMaxDynamicSharedMemorySize,
                             SMEM_BYTES);
        attr_set = true;
    }
    lstm_kernel<<<NBLK, NTHR, SMEM_BYTES>>>(input, Wih1, Whh1, bih1, bhh1,
                                            Wih2, Whh2, bih2, bhh2,
                                            Wlin, blin, out);
}